// round 1
// baseline (speedup 1.0000x reference)
#include <cuda_runtime.h>
#include <math.h>

// Problem constants
#define Bz 4
#define Cc 256
#define Oo 256
#define Gg 8
#define CG 32      // C/G
#define OG 32      // O/G
#define Hh 64
#define Ww 64
#define HW 4096
#define Nn 9
#define CO_OFF 144
#define CO_MASK 72
#define CO_ALL 216

// ---------------- scratch (device globals; no allocation allowed) ----------
__device__ float d_inp[(size_t)Bz * Gg * HW * CG];   // 16 MB  layout [b][g][p][c]
__device__ float d_x1[(size_t)Bz * Cc * HW];          // 16 MB  layout [b][c][p]
__device__ float d_offb[(size_t)Bz * CO_OFF * HW];    // 9 MB   layout [b][co][p]
__device__ float d_maskb[(size_t)Bz * CO_MASK * HW];  // 4.5 MB layout [b][co][p]
__device__ double d_stats[Bz * 2];
__device__ float d_mustd[Bz * 2];

// ---------------- K0: zero stats ------------------------------------------
__global__ void k_zero_stats() {
    int t = threadIdx.x;
    if (t < Bz * 2) d_stats[t] = 0.0;
}

// ---------------- K1: in_proj (1x1 conv) -> d_inp [b][g][p][c] ------------
// per batch GEMM: out[p][d] = sum_c x[b][c][p] * Wp[d][c]
__global__ __launch_bounds__(256) void k_inproj(const float* __restrict__ x,
                                                const float* __restrict__ Wp,
                                                const float* __restrict__ bp) {
    int b = blockIdx.z;
    int d0 = blockIdx.y * 64;
    int p0 = blockIdx.x * 64;
    __shared__ float Xs[16][64];
    __shared__ float Ws[16][65];
    int tid = threadIdx.x;
    int tx = tid & 15, ty = tid >> 4;
    float acc[4][4];
#pragma unroll
    for (int j = 0; j < 4; j++)
#pragma unroll
        for (int i = 0; i < 4; i++) acc[j][i] = 0.f;
    const float* xb = x + (size_t)b * Cc * HW;
    for (int c0 = 0; c0 < Cc; c0 += 16) {
        for (int idx = tid; idx < 1024; idx += 256) {
            int k = idx >> 6, pp = idx & 63;
            Xs[k][pp] = xb[(size_t)(c0 + k) * HW + p0 + pp];
        }
        for (int idx = tid; idx < 1024; idx += 256) {
            int dd = idx >> 4, k = idx & 15;
            Ws[k][dd] = Wp[(size_t)(d0 + dd) * Cc + c0 + k];
        }
        __syncthreads();
#pragma unroll
        for (int k = 0; k < 16; k++) {
            float a[4], bb[4];
#pragma unroll
            for (int j = 0; j < 4; j++) a[j] = Xs[k][ty * 4 + j];
#pragma unroll
            for (int i = 0; i < 4; i++) bb[i] = Ws[k][tx * 4 + i];
#pragma unroll
            for (int j = 0; j < 4; j++)
#pragma unroll
                for (int i = 0; i < 4; i++) acc[j][i] += a[j] * bb[i];
        }
        __syncthreads();
    }
#pragma unroll
    for (int j = 0; j < 4; j++) {
        int p = p0 + ty * 4 + j;
#pragma unroll
        for (int i = 0; i < 4; i++) {
            int d = d0 + tx * 4 + i;
            d_inp[(((size_t)b * Gg + (d >> 5)) * HW + p) * CG + (d & 31)] =
                acc[j][i] + bp[d];
        }
    }
}

// ---------------- K2: depthwise 3x3 conv + partial LN sums ----------------
__global__ __launch_bounds__(256) void k_dwconv(const float* __restrict__ x,
                                                const float* __restrict__ dww,
                                                const float* __restrict__ dwb) {
    int bc = blockIdx.x;
    int b = bc >> 8, c = bc & 255;
    const float* xp = x + (size_t)(b * Cc + c) * HW;
    float* outp = d_x1 + (size_t)(b * Cc + c) * HW;
    float wr[9];
#pragma unroll
    for (int t = 0; t < 9; t++) wr[t] = dww[c * 9 + t];
    float bias = dwb[c];
    double s1 = 0.0, s2 = 0.0;
    int tid = threadIdx.x;
    for (int p = tid; p < HW; p += 256) {
        int h = p >> 6, w = p & 63;
        float acc = bias;
#pragma unroll
        for (int dy = 0; dy < 3; dy++) {
            int yy = h + dy - 1;
            if ((unsigned)yy < (unsigned)Hh) {
#pragma unroll
                for (int dx = 0; dx < 3; dx++) {
                    int xx = w + dx - 1;
                    if ((unsigned)xx < (unsigned)Ww)
                        acc += xp[yy * Ww + xx] * wr[dy * 3 + dx];
                }
            }
        }
        outp[p] = acc;
        s1 += (double)acc;
        s2 += (double)acc * (double)acc;
    }
    __shared__ double rs1[256];
    __shared__ double rs2[256];
    rs1[tid] = s1;
    rs2[tid] = s2;
    __syncthreads();
    for (int off = 128; off > 0; off >>= 1) {
        if (tid < off) {
            rs1[tid] += rs1[tid + off];
            rs2[tid] += rs2[tid + off];
        }
        __syncthreads();
    }
    if (tid == 0) {
        atomicAdd(&d_stats[b * 2 + 0], rs1[0]);
        atomicAdd(&d_stats[b * 2 + 1], rs2[0]);
    }
}

// ---------------- K3: finalize LN stats -----------------------------------
__global__ void k_stats() {
    int b = threadIdx.x;
    if (b < Bz) {
        const double Np = (double)Cc * HW;
        double mu = d_stats[b * 2 + 0] / Np;
        double var = d_stats[b * 2 + 1] / Np - mu * mu;
        d_mustd[b * 2 + 0] = (float)mu;
        d_mustd[b * 2 + 1] = (float)(1.0 / sqrt(var + 1e-5));
    }
}

// ---------------- K4: apply LN + exact GELU in place ----------------------
__global__ __launch_bounds__(256) void k_lngelu() {
    size_t idx = (size_t)blockIdx.x * 256 + threadIdx.x;
    if (idx >= (size_t)Bz * Cc * HW) return;
    int b = (int)(idx / ((size_t)Cc * HW));
    float mu = d_mustd[b * 2 + 0];
    float istd = d_mustd[b * 2 + 1];
    float v = (d_x1[idx] - mu) * istd;
    d_x1[idx] = 0.5f * v * (1.f + erff(v * 0.70710678118654752f));
}

// ---------------- K5: heads conv (216 out ch, 3x3 pad 1) ------------------
#define CI_T 4
__global__ __launch_bounds__(256) void k_heads(const float* __restrict__ offw,
                                               const float* __restrict__ offbias,
                                               const float* __restrict__ maskw,
                                               const float* __restrict__ maskbias) {
    int b = blockIdx.z;
    int co0 = blockIdx.y * 16;
    int st = blockIdx.x;
    int ty0 = (st >> 2) * 16, tx0 = (st & 3) * 16;
    __shared__ float patch[CI_T][18][18];
    __shared__ float ws[CI_T][16][9];
    int tid = threadIdx.x;
    int cq = tid >> 6;     // 0..3 -> co quad
    int qid = tid & 63;    // pixel quad
    int py0 = (qid >> 3) * 2, px0 = (qid & 7) * 2;
    float acc[4][2][2];
#pragma unroll
    for (int i = 0; i < 4; i++)
#pragma unroll
        for (int a = 0; a < 2; a++)
#pragma unroll
            for (int bb = 0; bb < 2; bb++) acc[i][a][bb] = 0.f;

    const float* x1b = d_x1 + (size_t)b * Cc * HW;
    for (int ci0 = 0; ci0 < Cc; ci0 += CI_T) {
        for (int idx = tid; idx < CI_T * 324; idx += 256) {
            int ciL = idx / 324;
            int r = (idx % 324) / 18;
            int cc = idx % 18;
            int gy = ty0 + r - 1, gx = tx0 + cc - 1;
            float v = 0.f;
            if ((unsigned)gy < (unsigned)Hh && (unsigned)gx < (unsigned)Ww)
                v = x1b[(size_t)(ci0 + ciL) * HW + gy * Ww + gx];
            patch[ciL][r][cc] = v;
        }
        for (int idx = tid; idx < CI_T * 144; idx += 256) {
            int ciL = idx / 144;
            int rr = idx % 144;
            int col = rr / 9;
            int t = rr % 9;
            int co = co0 + col;
            int ci = ci0 + ciL;
            float w = 0.f;
            if (co < CO_OFF)
                w = offw[(size_t)co * 2304 + ci * 9 + t];
            else if (co < CO_ALL)
                w = maskw[(size_t)(co - CO_OFF) * 2304 + ci * 9 + t];
            ws[ciL][col][t] = w;
        }
        __syncthreads();
#pragma unroll
        for (int ciL = 0; ciL < CI_T; ciL++) {
            float tap[4][4];
#pragma unroll
            for (int r = 0; r < 4; r++)
#pragma unroll
                for (int c2 = 0; c2 < 4; c2++)
                    tap[r][c2] = patch[ciL][py0 + r][px0 + c2];
#pragma unroll
            for (int i = 0; i < 4; i++) {
#pragma unroll
                for (int dy = 0; dy < 3; dy++)
#pragma unroll
                    for (int dx = 0; dx < 3; dx++) {
                        float w = ws[ciL][cq * 4 + i][dy * 3 + dx];
                        acc[i][0][0] += w * tap[dy][dx];
                        acc[i][0][1] += w * tap[dy][dx + 1];
                        acc[i][1][0] += w * tap[dy + 1][dx];
                        acc[i][1][1] += w * tap[dy + 1][dx + 1];
                    }
            }
        }
        __syncthreads();
    }
#pragma unroll
    for (int i = 0; i < 4; i++) {
        int co = co0 + cq * 4 + i;
        if (co >= CO_ALL) continue;
        float bias = (co < CO_OFF) ? offbias[co] : maskbias[co - CO_OFF];
#pragma unroll
        for (int iy = 0; iy < 2; iy++)
#pragma unroll
            for (int ix = 0; ix < 2; ix++) {
                int p = (ty0 + py0 + iy) * Ww + tx0 + px0 + ix;
                float v = acc[i][iy][ix] + bias;
                if (co < CO_OFF)
                    d_offb[((size_t)b * CO_OFF + co) * HW + p] = v;
                else
                    d_maskb[((size_t)b * CO_MASK + (co - CO_OFF)) * HW + p] = v;
            }
    }
}

// ---------------- K6: softmax over consecutive flat groups of 9 -----------
// (matches reference's raw reshape (b,h,w,G,N) softmax on last axis)
__global__ __launch_bounds__(256) void k_softmax() {
    int gidx = blockIdx.x * 256 + threadIdx.x;  // Bz*CO_MASK*HW/9 = 131072 groups
    if (gidx >= Bz * CO_MASK * HW / 9) return;
    float* p = d_maskb + (size_t)gidx * 9;
    float v[9];
    float mx = -1e30f;
#pragma unroll
    for (int i = 0; i < 9; i++) {
        v[i] = p[i];
        mx = fmaxf(mx, v[i]);
    }
    float s = 0.f;
#pragma unroll
    for (int i = 0; i < 9; i++) {
        v[i] = expf(v[i] - mx);
        s += v[i];
    }
    float inv = 1.f / s;
#pragma unroll
    for (int i = 0; i < 9; i++) p[i] = v[i] * inv;
}

// ---------------- K7: deformable sampling + output einsum -----------------
// One warp per (b,g,pixel). lane = channel c within group.
__global__ __launch_bounds__(256) void k_sample(const float* __restrict__ outw,
                                                const float* __restrict__ outbias,
                                                float* __restrict__ out) {
    __shared__ float vs[8][288];        // [warp][c*9+n]
    __shared__ float wsm[32 * 292];     // [o][k] padded to 292 (conflict-free f4)
    int tid = threadIdx.x;
    int warp = tid >> 5, lane = tid & 31;
    long wg0 = (long)blockIdx.x * 8;
    int b = (int)(wg0 >> 15);
    int g = (int)((wg0 & 32767) >> 12);

    // load out_w slice for this group: w_r[g][o][c][n] = outw[(g*32+o)*288 + c*9+n]
    for (int idx = tid; idx < 32 * 288; idx += 256) {
        int o = idx / 288, k = idx % 288;
        wsm[o * 292 + k] = outw[(size_t)(g * OG + o) * 288 + k];
    }

    long wg = wg0 + warp;
    int p = (int)(wg & 4095);
    int h = p >> 6, w = p & 63;
    const float* inpg = d_inp + (size_t)(b * Gg + g) * HW * CG;
    const float* offp = d_offb + ((size_t)b * CO_OFF + g * 18) * HW + p;
    const float* mp = d_maskb + ((size_t)b * CO_MASK + g * Nn) * HW + p;

#pragma unroll
    for (int n = 0; n < Nn; n++) {
        float dy = offp[(size_t)(n * 2) * HW];
        float dx = offp[(size_t)(n * 2 + 1) * HW];
        float m = mp[(size_t)n * HW];
        float py = dy + (float)(n / 3) + (float)(h - 1);
        float px = dx + (float)(n % 3) + (float)(w - 1);
        float fy = floorf(py), fx = floorf(px);
        int y0 = (int)fy, x0 = (int)fx;
        float wy = py - fy, wx = px - fx;
        float v = 0.f;
        {
            int yi = y0, xi = x0;
            if ((unsigned)yi < (unsigned)Hh && (unsigned)xi < (unsigned)Ww)
                v += (1.f - wy) * (1.f - wx) * inpg[(size_t)(yi * Ww + xi) * CG + lane];
        }
        {
            int yi = y0, xi = x0 + 1;
            if ((unsigned)yi < (unsigned)Hh && (unsigned)xi < (unsigned)Ww)
                v += (1.f - wy) * wx * inpg[(size_t)(yi * Ww + xi) * CG + lane];
        }
        {
            int yi = y0 + 1, xi = x0;
            if ((unsigned)yi < (unsigned)Hh && (unsigned)xi < (unsigned)Ww)
                v += wy * (1.f - wx) * inpg[(size_t)(yi * Ww + xi) * CG + lane];
        }
        {
            int yi = y0 + 1, xi = x0 + 1;
            if ((unsigned)yi < (unsigned)Hh && (unsigned)xi < (unsigned)Ww)
                v += wy * wx * inpg[(size_t)(yi * Ww + xi) * CG + lane];
        }
        vs[warp][lane * 9 + n] = v * m;
    }
    __syncthreads();  // wsm visible + vs visible (per-warp anyway)

    // out[o] = sum_k vs[k] * wsm[o][k], lane = o
    const float4* vsv = reinterpret_cast<const float4*>(vs[warp]);
    const float4* wv = reinterpret_cast<const float4*>(&wsm[lane * 292]);
    float acc = 0.f;
#pragma unroll 8
    for (int k = 0; k < 72; k++) {
        float4 a = vsv[k];
        float4 ww = wv[k];
        acc += a.x * ww.x + a.y * ww.y + a.z * ww.z + a.w * ww.w;
    }
    out[((size_t)b * Oo + g * OG + lane) * HW + p] = acc + outbias[g * OG + lane];
}

// ---------------- launcher -------------------------------------------------
extern "C" void kernel_launch(void* const* d_in, const int* in_sizes, int n_in,
                              void* d_out, int out_size) {
    const float* x = (const float*)d_in[0];
    const float* in_proj_w = (const float*)d_in[1];
    const float* in_proj_b = (const float*)d_in[2];
    const float* dw_w = (const float*)d_in[3];
    const float* dw_b = (const float*)d_in[4];
    const float* off_w = (const float*)d_in[5];
    const float* off_b = (const float*)d_in[6];
    const float* mask_w = (const float*)d_in[7];
    const float* mask_b = (const float*)d_in[8];
    const float* out_w = (const float*)d_in[9];
    const float* out_b = (const float*)d_in[10];
    float* out = (float*)d_out;

    k_zero_stats<<<1, 32>>>();
    {
        dim3 grid(HW / 64, Oo / 64, Bz);
        k_inproj<<<grid, 256>>>(x, in_proj_w, in_proj_b);
    }
    k_dwconv<<<Bz * Cc, 256>>>(x, dw_w, dw_b);
    k_stats<<<1, 32>>>();
    {
        int total = Bz * Cc * HW;
        k_lngelu<<<(total + 255) / 256, 256>>>();
    }
    {
        dim3 grid(16, (CO_ALL + 15) / 16, Bz);  // (spatial tiles, co tiles, batch)
        k_heads<<<grid, 256>>>(off_w, off_b, mask_w, mask_b);
    }
    {
        int groups = Bz * CO_MASK * HW / 9;
        k_softmax<<<(groups + 255) / 256, 256>>>();
    }
    {
        int blocks = Bz * Gg * HW / 8;
        k_sample<<<blocks, 256>>>(out_w, out_b, out);
    }
}

// round 4
// speedup vs baseline: 1.1302x; 1.1302x over previous
#include <cuda_runtime.h>
#include <math.h>

// Problem constants
#define Bz 4
#define Cc 256
#define Oo 256
#define Gg 8
#define CG 32      // C/G
#define OG 32      // O/G
#define Hh 64
#define Ww 64
#define HW 4096
#define Nn 9
#define CO_OFF 144
#define CO_MASK 72
#define CO_ALL 216

// ---------------- scratch (device globals; no allocation allowed) ----------
__device__ float d_inp[(size_t)Bz * Gg * HW * CG];   // 16 MB  layout [b][g][p][c]
__device__ float d_x1[(size_t)Bz * Cc * HW];          // 16 MB  layout [b][c][p]
__device__ float d_offb[(size_t)Bz * CO_OFF * HW];    // 9 MB   layout [b][co][p]
__device__ float d_maskb[(size_t)Bz * CO_MASK * HW];  // 4.5 MB layout [b][co][p]
__device__ double d_stats[Bz * 2];
__device__ float d_mustd[Bz * 2];

// ---------------- K0: zero stats ------------------------------------------
__global__ void k_zero_stats() {
    int t = threadIdx.x;
    if (t < Bz * 2) d_stats[t] = 0.0;
}

// ---------------- K1: in_proj (1x1 conv) -> d_inp [b][g][p][c] ------------
// per batch GEMM: out[p][d] = sum_c x[b][c][p] * Wp[d][c]
__global__ __launch_bounds__(256) void k_inproj(const float* __restrict__ x,
                                                const float* __restrict__ Wp,
                                                const float* __restrict__ bp) {
    int b = blockIdx.z;
    int d0 = blockIdx.y * 64;
    int p0 = blockIdx.x * 64;
    __shared__ float Xs[16][64];
    __shared__ float Ws[16][65];
    int tid = threadIdx.x;
    int tx = tid & 15, ty = tid >> 4;
    float acc[4][4];
#pragma unroll
    for (int j = 0; j < 4; j++)
#pragma unroll
        for (int i = 0; i < 4; i++) acc[j][i] = 0.f;
    const float* xb = x + (size_t)b * Cc * HW;
    for (int c0 = 0; c0 < Cc; c0 += 16) {
        for (int idx = tid; idx < 1024; idx += 256) {
            int k = idx >> 6, pp = idx & 63;
            Xs[k][pp] = xb[(size_t)(c0 + k) * HW + p0 + pp];
        }
        for (int idx = tid; idx < 1024; idx += 256) {
            int dd = idx >> 4, k = idx & 15;
            Ws[k][dd] = Wp[(size_t)(d0 + dd) * Cc + c0 + k];
        }
        __syncthreads();
#pragma unroll
        for (int k = 0; k < 16; k++) {
            float a[4], bb[4];
#pragma unroll
            for (int j = 0; j < 4; j++) a[j] = Xs[k][ty * 4 + j];
#pragma unroll
            for (int i = 0; i < 4; i++) bb[i] = Ws[k][tx * 4 + i];
#pragma unroll
            for (int j = 0; j < 4; j++)
#pragma unroll
                for (int i = 0; i < 4; i++) acc[j][i] += a[j] * bb[i];
        }
        __syncthreads();
    }
#pragma unroll
    for (int j = 0; j < 4; j++) {
        int p = p0 + ty * 4 + j;
#pragma unroll
        for (int i = 0; i < 4; i++) {
            int d = d0 + tx * 4 + i;
            d_inp[(((size_t)b * Gg + (d >> 5)) * HW + p) * CG + (d & 31)] =
                acc[j][i] + bp[d];
        }
    }
}

// ---------------- K2: depthwise 3x3 conv + partial LN sums ----------------
__global__ __launch_bounds__(256) void k_dwconv(const float* __restrict__ x,
                                                const float* __restrict__ dww,
                                                const float* __restrict__ dwb) {
    int bc = blockIdx.x;
    int b = bc >> 8, c = bc & 255;
    const float* xp = x + (size_t)(b * Cc + c) * HW;
    float* outp = d_x1 + (size_t)(b * Cc + c) * HW;
    float wr[9];
#pragma unroll
    for (int t = 0; t < 9; t++) wr[t] = dww[c * 9 + t];
    float bias = dwb[c];
    double s1 = 0.0, s2 = 0.0;
    int tid = threadIdx.x;
    for (int p = tid; p < HW; p += 256) {
        int h = p >> 6, w = p & 63;
        float acc = bias;
#pragma unroll
        for (int dy = 0; dy < 3; dy++) {
            int yy = h + dy - 1;
            if ((unsigned)yy < (unsigned)Hh) {
#pragma unroll
                for (int dx = 0; dx < 3; dx++) {
                    int xx = w + dx - 1;
                    if ((unsigned)xx < (unsigned)Ww)
                        acc += xp[yy * Ww + xx] * wr[dy * 3 + dx];
                }
            }
        }
        outp[p] = acc;
        s1 += (double)acc;
        s2 += (double)acc * (double)acc;
    }
    __shared__ double rs1[256];
    __shared__ double rs2[256];
    rs1[tid] = s1;
    rs2[tid] = s2;
    __syncthreads();
    for (int off = 128; off > 0; off >>= 1) {
        if (tid < off) {
            rs1[tid] += rs1[tid + off];
            rs2[tid] += rs2[tid + off];
        }
        __syncthreads();
    }
    if (tid == 0) {
        atomicAdd(&d_stats[b * 2 + 0], rs1[0]);
        atomicAdd(&d_stats[b * 2 + 1], rs2[0]);
    }
}

// ---------------- K3: finalize LN stats -----------------------------------
__global__ void k_stats() {
    int b = threadIdx.x;
    if (b < Bz) {
        const double Np = (double)Cc * HW;
        double mu = d_stats[b * 2 + 0] / Np;
        double var = d_stats[b * 2 + 1] / Np - mu * mu;
        d_mustd[b * 2 + 0] = (float)mu;
        d_mustd[b * 2 + 1] = (float)(1.0 / sqrt(var + 1e-5));
    }
}

// ---------------- K4: apply LN + exact GELU in place ----------------------
__global__ __launch_bounds__(256) void k_lngelu() {
    size_t idx = (size_t)blockIdx.x * 256 + threadIdx.x;
    if (idx >= (size_t)Bz * Cc * HW) return;
    int b = (int)(idx / ((size_t)Cc * HW));
    float mu = d_mustd[b * 2 + 0];
    float istd = d_mustd[b * 2 + 1];
    float v = (d_x1[idx] - mu) * istd;
    d_x1[idx] = 0.5f * v * (1.f + erff(v * 0.70710678118654752f));
}

// ---------------- K5: heads conv as implicit-GEMM tf32 mma.sync -----------
// GEMM per batch: C[p][co] = sum_{k=(ci*9+t)} A[p][k] * W[k][co]
// A[p][ci*9+t] = x1[ci] sampled at tap t around pixel p (implicit im2col)
// W[k][co] = offw/maskw flat layout [co][ci*9+t]  (no reshuffle needed)
// Block tile: 128 pixels (2 image rows) x 112 co, K-chunk = 72 (8 ci x 9 taps)
__global__ __launch_bounds__(256) void k_heads_mma(const float* __restrict__ offw,
                                                   const float* __restrict__ offbias,
                                                   const float* __restrict__ maskw,
                                                   const float* __restrict__ maskbias) {
    int b = blockIdx.z;
    int p0 = blockIdx.x * 128;       // 2 image rows
    int n0 = blockIdx.y * 112;       // co base
    int h0 = p0 >> 6;                // first image row
    __shared__ float patch[8][4][66];   // [ciL][row h0-1..h0+2][col -1..64]
    __shared__ float ws[112][76];       // [co_local][k]  pad 76 -> conflict-free
    int tid = threadIdx.x;
    int warp = tid >> 5, lane = tid & 31;
    int wm = warp & 3, wn = warp >> 2;  // 4 M-warps x 2 N-warps
    int lg = lane >> 2, lt = lane & 3;

    float acc[2][7][4];
#pragma unroll
    for (int mt = 0; mt < 2; mt++)
#pragma unroll
        for (int nt = 0; nt < 7; nt++)
#pragma unroll
            for (int e = 0; e < 4; e++) acc[mt][nt][e] = 0.f;

    const float* x1b = d_x1 + (size_t)b * Cc * HW;

    for (int ci0 = 0; ci0 < Cc; ci0 += 8) {
        int kk0 = ci0 * 9;
        // stage input patch: 8 ci x 4 rows x 66 cols
        for (int idx = tid; idx < 8 * 264; idx += 256) {
            int ciL = idx / 264;
            int rem = idx - ciL * 264;
            int r = rem / 66;
            int c = rem - r * 66;
            int gy = h0 - 1 + r;
            int gx = c - 1;
            float v = 0.f;
            if ((unsigned)gy < (unsigned)Hh && (unsigned)gx < (unsigned)Ww)
                v = x1b[(size_t)(ci0 + ciL) * HW + gy * Ww + gx];
            patch[ciL][r][c] = v;
        }
        // stage weights: 112 co x 72 k (contiguous in global k!)
        for (int idx = tid; idx < 112 * 72; idx += 256) {
            int col = idx / 72;
            int k = idx - col * 72;
            int cog = n0 + col;
            float v = 0.f;
            if (cog < CO_OFF)
                v = offw[(size_t)cog * 2304 + kk0 + k];
            else if (cog < CO_ALL)
                v = maskw[(size_t)(cog - CO_OFF) * 2304 + kk0 + k];
            ws[col][k] = v;
        }
        __syncthreads();

#pragma unroll
        for (int ks = 0; ks < 9; ks++) {
            int kb = ks * 8;
            // decompose the two k-indices this thread touches
            int qa = kb + lt;
            int ciA = qa / 9; int ta = qa - ciA * 9;
            int kia = ta / 3; int kja = ta - kia * 3;
            int qb = qa + 4;
            int ciB = qb / 9; int tb = qb - ciB * 9;
            int kib = tb / 3; int kjb = tb - kib * 3;

            // B fragments (shared across both m-tiles)
            unsigned bfr[7][2];
#pragma unroll
            for (int nt = 0; nt < 7; nt++) {
                int n = wn * 56 + nt * 8 + lg;
                bfr[nt][0] = __float_as_uint(ws[n][kb + lt]);
                bfr[nt][1] = __float_as_uint(ws[n][kb + lt + 4]);
            }
#pragma unroll
            for (int mt = 0; mt < 2; mt++) {
                int rm = wm * 32 + mt * 16;
                int hL = rm >> 6;              // image row within tile (0/1)
                int w0 = (rm & 63) + lg;       // column of a0/a2 rows
                unsigned afr[4];
                afr[0] = __float_as_uint(patch[ciA][hL + kia][w0 + kja]);
                afr[1] = __float_as_uint(patch[ciA][hL + kia][w0 + 8 + kja]);
                afr[2] = __float_as_uint(patch[ciB][hL + kib][w0 + kjb]);
                afr[3] = __float_as_uint(patch[ciB][hL + kib][w0 + 8 + kjb]);
#pragma unroll
                for (int nt = 0; nt < 7; nt++) {
                    asm volatile(
                        "mma.sync.aligned.m16n8k8.row.col.f32.tf32.tf32.f32 "
                        "{%0,%1,%2,%3},{%4,%5,%6,%7},{%8,%9},{%0,%1,%2,%3};"
                        : "+f"(acc[mt][nt][0]), "+f"(acc[mt][nt][1]),
                          "+f"(acc[mt][nt][2]), "+f"(acc[mt][nt][3])
                        : "r"(afr[0]), "r"(afr[1]), "r"(afr[2]), "r"(afr[3]),
                          "r"(bfr[nt][0]), "r"(bfr[nt][1]));
                }
            }
        }
        __syncthreads();
    }

    // epilogue: bias + scatter to d_offb / d_maskb
#pragma unroll
    for (int mt = 0; mt < 2; mt++) {
        int rm = wm * 32 + mt * 16;
#pragma unroll
        for (int nt = 0; nt < 7; nt++) {
            int ncol = wn * 56 + nt * 8 + lt * 2;
#pragma unroll
            for (int e = 0; e < 4; e++) {
                int co = n0 + ncol + (e & 1);
                int p = p0 + rm + lg + ((e >> 1) * 8);
                float v = acc[mt][nt][e];
                if (co < CO_OFF)
                    d_offb[((size_t)b * CO_OFF + co) * HW + p] = v + offbias[co];
                else if (co < CO_ALL)
                    d_maskb[((size_t)b * CO_MASK + (co - CO_OFF)) * HW + p] =
                        v + maskbias[co - CO_OFF];
            }
        }
    }
}

// ---------------- K6: softmax over consecutive flat groups of 9 -----------
// (matches reference's raw reshape (b,h,w,G,N) softmax on last axis)
__global__ __launch_bounds__(256) void k_softmax() {
    int gidx = blockIdx.x * 256 + threadIdx.x;  // Bz*CO_MASK*HW/9 = 131072 groups
    if (gidx >= Bz * CO_MASK * HW / 9) return;
    float* p = d_maskb + (size_t)gidx * 9;
    float v[9];
    float mx = -1e30f;
#pragma unroll
    for (int i = 0; i < 9; i++) {
        v[i] = p[i];
        mx = fmaxf(mx, v[i]);
    }
    float s = 0.f;
#pragma unroll
    for (int i = 0; i < 9; i++) {
        v[i] = expf(v[i] - mx);
        s += v[i];
    }
    float inv = 1.f / s;
#pragma unroll
    for (int i = 0; i < 9; i++) p[i] = v[i] * inv;
}

// ---------------- K7: deformable sampling + output einsum -----------------
// One warp per (b,g,pixel). lane = channel c within group.
__global__ __launch_bounds__(256) void k_sample(const float* __restrict__ outw,
                                                const float* __restrict__ outbias,
                                                float* __restrict__ out) {
    __shared__ float vs[8][288];        // [warp][c*9+n]
    __shared__ float wsm[32 * 292];     // [o][k] padded to 292 (conflict-free f4)
    int tid = threadIdx.x;
    int warp = tid >> 5, lane = tid & 31;
    long wg0 = (long)blockIdx.x * 8;
    int b = (int)(wg0 >> 15);
    int g = (int)((wg0 & 32767) >> 12);

    // load out_w slice for this group: w_r[g][o][c][n] = outw[(g*32+o)*288 + c*9+n]
    for (int idx = tid; idx < 32 * 288; idx += 256) {
        int o = idx / 288, k = idx % 288;
        wsm[o * 292 + k] = outw[(size_t)(g * OG + o) * 288 + k];
    }

    long wg = wg0 + warp;
    int p = (int)(wg & 4095);
    int h = p >> 6, w = p & 63;
    const float* inpg = d_inp + (size_t)(b * Gg + g) * HW * CG;
    const float* offp = d_offb + ((size_t)b * CO_OFF + g * 18) * HW + p;
    const float* mp = d_maskb + ((size_t)b * CO_MASK + g * Nn) * HW + p;

#pragma unroll
    for (int n = 0; n < Nn; n++) {
        float dy = offp[(size_t)(n * 2) * HW];
        float dx = offp[(size_t)(n * 2 + 1) * HW];
        float m = mp[(size_t)n * HW];
        float py = dy + (float)(n / 3) + (float)(h - 1);
        float px = dx + (float)(n % 3) + (float)(w - 1);
        float fy = floorf(py), fx = floorf(px);
        int y0 = (int)fy, x0 = (int)fx;
        float wy = py - fy, wx = px - fx;
        float v = 0.f;
        {
            int yi = y0, xi = x0;
            if ((unsigned)yi < (unsigned)Hh && (unsigned)xi < (unsigned)Ww)
                v += (1.f - wy) * (1.f - wx) * inpg[(size_t)(yi * Ww + xi) * CG + lane];
        }
        {
            int yi = y0, xi = x0 + 1;
            if ((unsigned)yi < (unsigned)Hh && (unsigned)xi < (unsigned)Ww)
                v += (1.f - wy) * wx * inpg[(size_t)(yi * Ww + xi) * CG + lane];
        }
        {
            int yi = y0 + 1, xi = x0;
            if ((unsigned)yi < (unsigned)Hh && (unsigned)xi < (unsigned)Ww)
                v += wy * (1.f - wx) * inpg[(size_t)(yi * Ww + xi) * CG + lane];
        }
        {
            int yi = y0 + 1, xi = x0 + 1;
            if ((unsigned)yi < (unsigned)Hh && (unsigned)xi < (unsigned)Ww)
                v += wy * wx * inpg[(size_t)(yi * Ww + xi) * CG + lane];
        }
        vs[warp][lane * 9 + n] = v * m;
    }
    __syncthreads();  // wsm visible + vs visible (per-warp anyway)

    // out[o] = sum_k vs[k] * wsm[o][k], lane = o
    const float4* vsv = reinterpret_cast<const float4*>(vs[warp]);
    const float4* wv = reinterpret_cast<const float4*>(&wsm[lane * 292]);
    float acc = 0.f;
#pragma unroll 8
    for (int k = 0; k < 72; k++) {
        float4 a = vsv[k];
        float4 ww = wv[k];
        acc += a.x * ww.x + a.y * ww.y + a.z * ww.z + a.w * ww.w;
    }
    out[((size_t)b * Oo + g * OG + lane) * HW + p] = acc + outbias[g * OG + lane];
}

// ---------------- launcher -------------------------------------------------
extern "C" void kernel_launch(void* const* d_in, const int* in_sizes, int n_in,
                              void* d_out, int out_size) {
    const float* x = (const float*)d_in[0];
    const float* in_proj_w = (const float*)d_in[1];
    const float* in_proj_b = (const float*)d_in[2];
    const float* dw_w = (const float*)d_in[3];
    const float* dw_b = (const float*)d_in[4];
    const float* off_w = (const float*)d_in[5];
    const float* off_b = (const float*)d_in[6];
    const float* mask_w = (const float*)d_in[7];
    const float* mask_b = (const float*)d_in[8];
    const float* out_w = (const float*)d_in[9];
    const float* out_b = (const float*)d_in[10];
    float* out = (float*)d_out;

    k_zero_stats<<<1, 32>>>();
    {
        dim3 grid(HW / 64, Oo / 64, Bz);
        k_inproj<<<grid, 256>>>(x, in_proj_w, in_proj_b);
    }
    k_dwconv<<<Bz * Cc, 256>>>(x, dw_w, dw_b);
    k_stats<<<1, 32>>>();
    {
        int total = Bz * Cc * HW;
        k_lngelu<<<(total + 255) / 256, 256>>>();
    }
    {
        dim3 grid(HW / 128, 2, Bz);  // (pixel tiles, co tiles of 112, batch)
        k_heads_mma<<<grid, 256>>>(off_w, off_b, mask_w, mask_b);
    }
    {
        int groups = Bz * CO_MASK * HW / 9;
        k_softmax<<<(groups + 255) / 256, 256>>>();
    }
    {
        int blocks = Bz * Gg * HW / 8;
        k_sample<<<blocks, 256>>>(out_w, out_b, out);
    }
}

// round 5
// speedup vs baseline: 1.9084x; 1.6886x over previous
#include <cuda_runtime.h>
#include <math.h>
#include <stdint.h>

// Problem constants
#define Bz 4
#define Cc 256
#define Oo 256
#define Gg 8
#define CG 32      // C/G
#define OG 32      // O/G
#define Hh 64
#define Ww 64
#define HW 4096
#define Nn 9
#define CO_OFF 144
#define CO_MASK 72
#define CO_ALL 216

// ---------------- scratch (device globals; no allocation allowed) ----------
__device__ float d_inp[(size_t)Bz * Gg * HW * CG];   // 16 MB  layout [b][g][p][c]
__device__ float d_x1[(size_t)Bz * Cc * HW];          // 16 MB  layout [b][c][p]
__device__ float d_offb[(size_t)Bz * CO_OFF * HW];    // 9 MB   layout [b][co][p]
__device__ float d_maskb[(size_t)Bz * CO_MASK * HW];  // 4.5 MB layout [b][co][p]
__device__ double d_stats[Bz * 2];
__device__ float d_mustd[Bz * 2];

#define CP16(dst, src) \
    asm volatile("cp.async.cg.shared.global [%0], [%1], 16;" ::"r"(dst), "l"(src) : "memory")
#define CP_COMMIT() asm volatile("cp.async.commit_group;" ::: "memory")
#define CP_WAIT1() asm volatile("cp.async.wait_group 1;" ::: "memory")

// ---------------- K0: zero stats ------------------------------------------
__global__ void k_zero_stats() {
    int t = threadIdx.x;
    if (t < Bz * 2) d_stats[t] = 0.0;
}

// ---------------- K1: in_proj (1x1 conv) -> d_inp [b][g][p][c] ------------
__global__ __launch_bounds__(256) void k_inproj(const float* __restrict__ x,
                                                const float* __restrict__ Wp,
                                                const float* __restrict__ bp) {
    int b = blockIdx.z;
    int d0 = blockIdx.y * 64;
    int p0 = blockIdx.x * 64;
    __shared__ float Xs[16][64];
    __shared__ float Ws[16][65];
    int tid = threadIdx.x;
    int tx = tid & 15, ty = tid >> 4;
    float acc[4][4];
#pragma unroll
    for (int j = 0; j < 4; j++)
#pragma unroll
        for (int i = 0; i < 4; i++) acc[j][i] = 0.f;
    const float* xb = x + (size_t)b * Cc * HW;
    for (int c0 = 0; c0 < Cc; c0 += 16) {
        for (int idx = tid; idx < 1024; idx += 256) {
            int k = idx >> 6, pp = idx & 63;
            Xs[k][pp] = xb[(size_t)(c0 + k) * HW + p0 + pp];
        }
        for (int idx = tid; idx < 1024; idx += 256) {
            int dd = idx >> 4, k = idx & 15;
            Ws[k][dd] = Wp[(size_t)(d0 + dd) * Cc + c0 + k];
        }
        __syncthreads();
#pragma unroll
        for (int k = 0; k < 16; k++) {
            float a[4], bb[4];
#pragma unroll
            for (int j = 0; j < 4; j++) a[j] = Xs[k][ty * 4 + j];
#pragma unroll
            for (int i = 0; i < 4; i++) bb[i] = Ws[k][tx * 4 + i];
#pragma unroll
            for (int j = 0; j < 4; j++)
#pragma unroll
                for (int i = 0; i < 4; i++) acc[j][i] += a[j] * bb[i];
        }
        __syncthreads();
    }
#pragma unroll
    for (int j = 0; j < 4; j++) {
        int p = p0 + ty * 4 + j;
#pragma unroll
        for (int i = 0; i < 4; i++) {
            int d = d0 + tx * 4 + i;
            d_inp[(((size_t)b * Gg + (d >> 5)) * HW + p) * CG + (d & 31)] =
                acc[j][i] + bp[d];
        }
    }
}

// ---------------- K2: depthwise 3x3 conv + partial LN sums ----------------
__global__ __launch_bounds__(256) void k_dwconv(const float* __restrict__ x,
                                                const float* __restrict__ dww,
                                                const float* __restrict__ dwb) {
    int bc = blockIdx.x;
    int b = bc >> 8, c = bc & 255;
    const float* xp = x + (size_t)(b * Cc + c) * HW;
    float* outp = d_x1 + (size_t)(b * Cc + c) * HW;
    float wr[9];
#pragma unroll
    for (int t = 0; t < 9; t++) wr[t] = dww[c * 9 + t];
    float bias = dwb[c];
    double s1 = 0.0, s2 = 0.0;
    int tid = threadIdx.x;
    for (int p = tid; p < HW; p += 256) {
        int h = p >> 6, w = p & 63;
        float acc = bias;
#pragma unroll
        for (int dy = 0; dy < 3; dy++) {
            int yy = h + dy - 1;
            if ((unsigned)yy < (unsigned)Hh) {
#pragma unroll
                for (int dx = 0; dx < 3; dx++) {
                    int xx = w + dx - 1;
                    if ((unsigned)xx < (unsigned)Ww)
                        acc += xp[yy * Ww + xx] * wr[dy * 3 + dx];
                }
            }
        }
        outp[p] = acc;
        s1 += (double)acc;
        s2 += (double)acc * (double)acc;
    }
    __shared__ double rs1[256];
    __shared__ double rs2[256];
    rs1[tid] = s1;
    rs2[tid] = s2;
    __syncthreads();
    for (int off = 128; off > 0; off >>= 1) {
        if (tid < off) {
            rs1[tid] += rs1[tid + off];
            rs2[tid] += rs2[tid + off];
        }
        __syncthreads();
    }
    if (tid == 0) {
        atomicAdd(&d_stats[b * 2 + 0], rs1[0]);
        atomicAdd(&d_stats[b * 2 + 1], rs2[0]);
    }
}

// ---------------- K3: finalize LN stats -----------------------------------
__global__ void k_stats() {
    int b = threadIdx.x;
    if (b < Bz) {
        const double Np = (double)Cc * HW;
        double mu = d_stats[b * 2 + 0] / Np;
        double var = d_stats[b * 2 + 1] / Np - mu * mu;
        d_mustd[b * 2 + 0] = (float)mu;
        d_mustd[b * 2 + 1] = (float)(1.0 / sqrt(var + 1e-5));
    }
}

// ---------------- K4: apply LN + exact GELU in place ----------------------
__global__ __launch_bounds__(256) void k_lngelu() {
    size_t idx = (size_t)blockIdx.x * 256 + threadIdx.x;
    if (idx >= (size_t)Bz * Cc * HW) return;
    int b = (int)(idx / ((size_t)Cc * HW));
    float mu = d_mustd[b * 2 + 0];
    float istd = d_mustd[b * 2 + 1];
    float v = (d_x1[idx] - mu) * istd;
    d_x1[idx] = 0.5f * v * (1.f + erff(v * 0.70710678118654752f));
}

// ---------------- K5: heads conv as implicit-GEMM tf32 mma.sync -----------
// cp.async double-buffered staging. Block tile: 128 pixels x 112 co.
// Dynamic smem layout (floats):
//   patch: [2][8][4][72]  (data cols 4..67 = gx 0..63; cols 0..3,68..71 zero)
//   ws   : [2][112][76]
#define PATCH_F (2 * 8 * 4 * 72)     // 4608 floats
#define WS_F (2 * 112 * 76)          // 17024 floats
#define HEADS_SMEM ((PATCH_F + WS_F) * 4)  // 86528 bytes

__global__ __launch_bounds__(256) void k_heads_mma(const float* __restrict__ offw,
                                                   const float* __restrict__ offbias,
                                                   const float* __restrict__ maskw,
                                                   const float* __restrict__ maskbias) {
    extern __shared__ float dynsm[];
    float* patchp = dynsm;                 // [(buf*8+ci)*4+r]*72 + col
    float* wsp = dynsm + PATCH_F;          // [(buf*112+col)*76 + k]

    int b = blockIdx.z;
    int p0 = blockIdx.x * 128;
    int n0 = blockIdx.y * 112;
    int h0 = p0 >> 6;
    int tid = threadIdx.x;
    int warp = tid >> 5, lane = tid & 31;
    int wm = warp & 3, wn = warp >> 2;
    int lg = lane >> 2, lt = lane & 3;

    const float* x1b = d_x1 + (size_t)b * Cc * HW;
    uint32_t smem_u32 = (uint32_t)__cvta_generic_to_shared(dynsm);
    uint32_t ws_u32 = smem_u32 + PATCH_F * 4;

    // zero both buffers once (halo cols / invalid rows / co>=216 stay zero)
    for (int idx = tid; idx < PATCH_F + WS_F; idx += 256) dynsm[idx] = 0.f;
    __syncthreads();

    float acc[2][7][4];
#pragma unroll
    for (int mt = 0; mt < 2; mt++)
#pragma unroll
        for (int nt = 0; nt < 7; nt++)
#pragma unroll
            for (int e = 0; e < 4; e++) acc[mt][nt][e] = 0.f;

    // staging helper (inlined twice)
#define STAGE(CHUNK, BUF)                                                          \
    {                                                                              \
        int ci0_ = (CHUNK) * 8;                                                    \
        int kk0_ = ci0_ * 9;                                                       \
        for (int idx = tid; idx < 2528; idx += 256) {                              \
            if (idx < 512) {                                                       \
                int ciL = idx >> 6;                                                \
                int r = (idx >> 4) & 3;                                            \
                int j = idx & 15;                                                  \
                int gy = h0 - 1 + r;                                               \
                if ((unsigned)gy < (unsigned)Hh) {                                 \
                    const float* src =                                             \
                        x1b + (size_t)(ci0_ + ciL) * HW + gy * Ww + j * 4;         \
                    uint32_t dst = smem_u32 +                                      \
                        ((((BUF) * 8 + ciL) * 4 + r) * 72 + 4 + j * 4) * 4;        \
                    CP16(dst, src);                                                \
                }                                                                  \
            } else {                                                               \
                int t = idx - 512;                                                 \
                int col = t / 18;                                                  \
                int j = t - col * 18;                                              \
                int cog = n0 + col;                                                \
                if (cog < CO_ALL) {                                                \
                    const float* src =                                             \
                        (cog < CO_OFF ? offw + (size_t)cog * 2304                  \
                                      : maskw + (size_t)(cog - CO_OFF) * 2304) +   \
                        kk0_ + j * 4;                                              \
                    uint32_t dst =                                                 \
                        ws_u32 + (((BUF) * 112 + col) * 76 + j * 4) * 4;           \
                    CP16(dst, src);                                                \
                }                                                                  \
            }                                                                      \
        }                                                                          \
        CP_COMMIT();                                                               \
    }

    STAGE(0, 0);
    for (int c = 0; c < 32; c++) {
        int buf = c & 1;
        if (c < 31) {
            STAGE(c + 1, buf ^ 1);
        } else {
            CP_COMMIT();  // empty group keeps wait count uniform
        }
        CP_WAIT1();
        __syncthreads();

        const float* pb = patchp + (size_t)buf * 8 * 4 * 72;
        const float* wb = wsp + (size_t)buf * 112 * 76;
#pragma unroll
        for (int ks = 0; ks < 9; ks++) {
            int kb = ks * 8;
            int qa = kb + lt;
            int ciA = qa / 9; int ta = qa - ciA * 9;
            int kia = ta / 3; int kja = ta - kia * 3;
            int qb = qa + 4;
            int ciB = qb / 9; int tb = qb - ciB * 9;
            int kib = tb / 3; int kjb = tb - kib * 3;

            unsigned bfr[7][2];
#pragma unroll
            for (int nt = 0; nt < 7; nt++) {
                int n = wn * 56 + nt * 8 + lg;
                bfr[nt][0] = __float_as_uint(wb[n * 76 + kb + lt]);
                bfr[nt][1] = __float_as_uint(wb[n * 76 + kb + lt + 4]);
            }
#pragma unroll
            for (int mt = 0; mt < 2; mt++) {
                int rm = wm * 32 + mt * 16;
                int hL = rm >> 6;
                int w0 = (rm & 63) + lg;
                unsigned afr[4];
                afr[0] = __float_as_uint(pb[(ciA * 4 + hL + kia) * 72 + 3 + w0 + kja]);
                afr[1] = __float_as_uint(pb[(ciA * 4 + hL + kia) * 72 + 11 + w0 + kja]);
                afr[2] = __float_as_uint(pb[(ciB * 4 + hL + kib) * 72 + 3 + w0 + kjb]);
                afr[3] = __float_as_uint(pb[(ciB * 4 + hL + kib) * 72 + 11 + w0 + kjb]);
#pragma unroll
                for (int nt = 0; nt < 7; nt++) {
                    asm volatile(
                        "mma.sync.aligned.m16n8k8.row.col.f32.tf32.tf32.f32 "
                        "{%0,%1,%2,%3},{%4,%5,%6,%7},{%8,%9},{%0,%1,%2,%3};"
                        : "+f"(acc[mt][nt][0]), "+f"(acc[mt][nt][1]),
                          "+f"(acc[mt][nt][2]), "+f"(acc[mt][nt][3])
                        : "r"(afr[0]), "r"(afr[1]), "r"(afr[2]), "r"(afr[3]),
                          "r"(bfr[nt][0]), "r"(bfr[nt][1]));
                }
            }
        }
        __syncthreads();
    }
#undef STAGE

    // epilogue: bias + scatter to d_offb / d_maskb
#pragma unroll
    for (int mt = 0; mt < 2; mt++) {
        int rm = wm * 32 + mt * 16;
#pragma unroll
        for (int nt = 0; nt < 7; nt++) {
            int ncol = wn * 56 + nt * 8 + lt * 2;
#pragma unroll
            for (int e = 0; e < 4; e++) {
                int co = n0 + ncol + (e & 1);
                int p = p0 + rm + lg + ((e >> 1) * 8);
                float v = acc[mt][nt][e];
                if (co < CO_OFF)
                    d_offb[((size_t)b * CO_OFF + co) * HW + p] = v + offbias[co];
                else if (co < CO_ALL)
                    d_maskb[((size_t)b * CO_MASK + (co - CO_OFF)) * HW + p] =
                        v + maskbias[co - CO_OFF];
            }
        }
    }
}

// ---------------- K6: softmax over consecutive flat groups of 9 -----------
__global__ __launch_bounds__(256) void k_softmax() {
    __shared__ float sm[2304];
    int tid = threadIdx.x;
    size_t base = (size_t)blockIdx.x * 2304;
#pragma unroll
    for (int idx = tid; idx < 2304; idx += 256) sm[idx] = d_maskb[base + idx];
    __syncthreads();
    float* p = sm + tid * 9;
    float v[9];
    float mx = -1e30f;
#pragma unroll
    for (int i = 0; i < 9; i++) {
        v[i] = p[i];
        mx = fmaxf(mx, v[i]);
    }
    float s = 0.f;
#pragma unroll
    for (int i = 0; i < 9; i++) {
        v[i] = expf(v[i] - mx);
        s += v[i];
    }
    float inv = 1.f / s;
#pragma unroll
    for (int i = 0; i < 9; i++) p[i] = v[i] * inv;
    __syncthreads();
#pragma unroll
    for (int idx = tid; idx < 2304; idx += 256) d_maskb[base + idx] = sm[idx];
}

// ---------------- K7: deformable sampling + output einsum -----------------
// 128 pixels per block (8 warps x 16 pixels), weights loaded once per block.
// Dynamic smem (floats): wsm 32*292 = 9344 | vs 8*4*288 = 9216 | outbuf 32*129 = 4128
#define WSM_F 9344
#define VS_F (8 * 4 * 288)
#define OUTB_F (32 * 129)
#define SAMPLE_SMEM ((WSM_F + VS_F + OUTB_F) * 4)  // 90752 bytes

__global__ __launch_bounds__(256) void k_sample(const float* __restrict__ outw,
                                                const float* __restrict__ outbias,
                                                float* __restrict__ out) {
    extern __shared__ float sm2[];
    float* wsm = sm2;
    float* vsbase = sm2 + WSM_F;
    float* outbf = sm2 + WSM_F + VS_F;

    int tid = threadIdx.x;
    int warp = tid >> 5, lane = tid & 31;
    int bg = blockIdx.x >> 5;
    int b = bg >> 3, g = bg & 7;
    int p0 = (blockIdx.x & 31) * 128;

    // load out_w slice for this group once per block
    for (int idx = tid; idx < 32 * 288; idx += 256) {
        int o = idx / 288, k = idx - o * 288;
        wsm[o * 292 + k] = outw[(size_t)(g * OG + o) * 288 + k];
    }
    __syncthreads();

    const float* inpg = d_inp + (size_t)(b * Gg + g) * HW * CG;
    const float* offbase = d_offb + ((size_t)b * CO_OFF + g * 18) * HW;
    const float* mbase = d_maskb + ((size_t)b * CO_MASK + g * Nn) * HW;
    float* vsw = vsbase + warp * 4 * 288;
    const float4* wv = reinterpret_cast<const float4*>(&wsm[lane * 292]);

    int pbase = p0 + warp * 16;
#pragma unroll 1
    for (int pass = 0; pass < 4; pass++) {
#pragma unroll
        for (int i = 0; i < 4; i++) {
            int p = pbase + pass * 4 + i;
            int h = p >> 6, w = p & 63;
            const float* offp = offbase + p;
            const float* mp = mbase + p;
            float* vsd = vsw + i * 288;
#pragma unroll
            for (int n = 0; n < Nn; n++) {
                float dy = offp[(size_t)(n * 2) * HW];
                float dx = offp[(size_t)(n * 2 + 1) * HW];
                float m = mp[(size_t)n * HW];
                float py = dy + (float)(n / 3) + (float)(h - 1);
                float px = dx + (float)(n % 3) + (float)(w - 1);
                float fy = floorf(py), fx = floorf(px);
                int y0 = (int)fy, x0 = (int)fx;
                float wy = py - fy, wx = px - fx;
                float v = 0.f;
                {
                    int yi = y0, xi = x0;
                    if ((unsigned)yi < (unsigned)Hh && (unsigned)xi < (unsigned)Ww)
                        v += (1.f - wy) * (1.f - wx) *
                             inpg[(size_t)(yi * Ww + xi) * CG + lane];
                }
                {
                    int yi = y0, xi = x0 + 1;
                    if ((unsigned)yi < (unsigned)Hh && (unsigned)xi < (unsigned)Ww)
                        v += (1.f - wy) * wx *
                             inpg[(size_t)(yi * Ww + xi) * CG + lane];
                }
                {
                    int yi = y0 + 1, xi = x0;
                    if ((unsigned)yi < (unsigned)Hh && (unsigned)xi < (unsigned)Ww)
                        v += wy * (1.f - wx) *
                             inpg[(size_t)(yi * Ww + xi) * CG + lane];
                }
                {
                    int yi = y0 + 1, xi = x0 + 1;
                    if ((unsigned)yi < (unsigned)Hh && (unsigned)xi < (unsigned)Ww)
                        v += wy * wx * inpg[(size_t)(yi * Ww + xi) * CG + lane];
                }
                vsd[lane * 9 + n] = v * m;
            }
        }
        __syncwarp();

        // einsum: 4 pixels share each weight load
        const float4* v0 = reinterpret_cast<const float4*>(vsw);
        const float4* v1 = reinterpret_cast<const float4*>(vsw + 288);
        const float4* v2 = reinterpret_cast<const float4*>(vsw + 576);
        const float4* v3 = reinterpret_cast<const float4*>(vsw + 864);
        float a0 = 0.f, a1 = 0.f, a2 = 0.f, a3 = 0.f;
#pragma unroll 8
        for (int k = 0; k < 72; k++) {
            float4 ww = wv[k];
            float4 q;
            q = v0[k]; a0 += q.x * ww.x + q.y * ww.y + q.z * ww.z + q.w * ww.w;
            q = v1[k]; a1 += q.x * ww.x + q.y * ww.y + q.z * ww.z + q.w * ww.w;
            q = v2[k]; a2 += q.x * ww.x + q.y * ww.y + q.z * ww.z + q.w * ww.w;
            q = v3[k]; a3 += q.x * ww.x + q.y * ww.y + q.z * ww.z + q.w * ww.w;
        }
        int colb = warp * 16 + pass * 4;
        outbf[lane * 129 + colb + 0] = a0;
        outbf[lane * 129 + colb + 1] = a1;
        outbf[lane * 129 + colb + 2] = a2;
        outbf[lane * 129 + colb + 3] = a3;
        __syncwarp();
    }
    __syncthreads();

    // coalesced writeback: 32 o x 128 pixels
    for (int idx = tid; idx < 4096; idx += 256) {
        int o = idx >> 7, pp = idx & 127;
        out[((size_t)b * Oo + g * OG + o) * HW + p0 + pp] =
            outbf[o * 129 + pp] + outbias[g * OG + o];
    }
}

// ---------------- launcher -------------------------------------------------
extern "C" void kernel_launch(void* const* d_in, const int* in_sizes, int n_in,
                              void* d_out, int out_size) {
    const float* x = (const float*)d_in[0];
    const float* in_proj_w = (const float*)d_in[1];
    const float* in_proj_b = (const float*)d_in[2];
    const float* dw_w = (const float*)d_in[3];
    const float* dw_b = (const float*)d_in[4];
    const float* off_w = (const float*)d_in[5];
    const float* off_b = (const float*)d_in[6];
    const float* mask_w = (const float*)d_in[7];
    const float* mask_b = (const float*)d_in[8];
    const float* out_w = (const float*)d_in[9];
    const float* out_b = (const float*)d_in[10];
    float* out = (float*)d_out;

    // allow >48KB dynamic smem (idempotent; not a memory allocation)
    cudaFuncSetAttribute(k_heads_mma, cudaFuncAttributeMaxDynamicSharedMemorySize,
                         HEADS_SMEM);
    cudaFuncSetAttribute(k_sample, cudaFuncAttributeMaxDynamicSharedMemorySize,
                         SAMPLE_SMEM);

    k_zero_stats<<<1, 32>>>();
    {
        dim3 grid(HW / 64, Oo / 64, Bz);
        k_inproj<<<grid, 256>>>(x, in_proj_w, in_proj_b);
    }
    k_dwconv<<<Bz * Cc, 256>>>(x, dw_w, dw_b);
    k_stats<<<1, 32>>>();
    {
        int total = Bz * Cc * HW;
        k_lngelu<<<(total + 255) / 256, 256>>>();
    }
    {
        dim3 grid(HW / 128, 2, Bz);
        k_heads_mma<<<grid, 256, HEADS_SMEM>>>(off_w, off_b, mask_w, mask_b);
    }
    {
        k_softmax<<<512, 256>>>();
    }
    {
        k_sample<<<1024, 256, SAMPLE_SMEM>>>(out_w, out_b, out);
    }
}

// round 6
// speedup vs baseline: 2.0673x; 1.0832x over previous
#include <cuda_runtime.h>
#include <math.h>
#include <stdint.h>

// Problem constants
#define Bz 4
#define Cc 256
#define Oo 256
#define Gg 8
#define CG 32      // C/G
#define OG 32      // O/G
#define Hh 64
#define Ww 64
#define HW 4096
#define Nn 9
#define CO_OFF 144
#define CO_MASK 72
#define CO_ALL 216

// ---------------- scratch (device globals; no allocation allowed) ----------
__device__ float d_inp[(size_t)Bz * Gg * HW * CG];   // 16 MB  layout [b][g][p][c]
__device__ float d_x1[(size_t)Bz * Cc * HW];          // 16 MB  layout [b][c][p]
__device__ float d_offb[(size_t)Bz * CO_OFF * HW];    // 9 MB   layout [b][co][p]
__device__ float d_maskb[(size_t)Bz * CO_MASK * HW];  // 4.5 MB layout [b][co][p]
__device__ double d_stats[Bz * 2];
__device__ float d_mustd[Bz * 2];

#define CP16(dst, src) \
    asm volatile("cp.async.cg.shared.global [%0], [%1], 16;" ::"r"(dst), "l"(src) : "memory")
#define CP_COMMIT() asm volatile("cp.async.commit_group;" ::: "memory")
#define CP_WAIT1() asm volatile("cp.async.wait_group 1;" ::: "memory")

// ---------------- K0: zero stats ------------------------------------------
__global__ void k_zero_stats() {
    int t = threadIdx.x;
    if (t < Bz * 2) d_stats[t] = 0.0;
}

// ---------------- K1: in_proj (1x1 conv) -> d_inp [b][g][p][c] ------------
__global__ __launch_bounds__(256) void k_inproj(const float* __restrict__ x,
                                                const float* __restrict__ Wp,
                                                const float* __restrict__ bp) {
    int b = blockIdx.z;
    int d0 = blockIdx.y * 64;
    int p0 = blockIdx.x * 64;
    __shared__ float Xs[16][64];
    __shared__ float Ws[16][65];
    int tid = threadIdx.x;
    int tx = tid & 15, ty = tid >> 4;
    float acc[4][4];
#pragma unroll
    for (int j = 0; j < 4; j++)
#pragma unroll
        for (int i = 0; i < 4; i++) acc[j][i] = 0.f;
    const float* xb = x + (size_t)b * Cc * HW;
    for (int c0 = 0; c0 < Cc; c0 += 16) {
        for (int idx = tid; idx < 1024; idx += 256) {
            int k = idx >> 6, pp = idx & 63;
            Xs[k][pp] = xb[(size_t)(c0 + k) * HW + p0 + pp];
        }
        for (int idx = tid; idx < 1024; idx += 256) {
            int dd = idx >> 4, k = idx & 15;
            Ws[k][dd] = Wp[(size_t)(d0 + dd) * Cc + c0 + k];
        }
        __syncthreads();
#pragma unroll
        for (int k = 0; k < 16; k++) {
            float a[4], bb[4];
#pragma unroll
            for (int j = 0; j < 4; j++) a[j] = Xs[k][ty * 4 + j];
#pragma unroll
            for (int i = 0; i < 4; i++) bb[i] = Ws[k][tx * 4 + i];
#pragma unroll
            for (int j = 0; j < 4; j++)
#pragma unroll
                for (int i = 0; i < 4; i++) acc[j][i] += a[j] * bb[i];
        }
        __syncthreads();
    }
#pragma unroll
    for (int j = 0; j < 4; j++) {
        int p = p0 + ty * 4 + j;
#pragma unroll
        for (int i = 0; i < 4; i++) {
            int d = d0 + tx * 4 + i;
            d_inp[(((size_t)b * Gg + (d >> 5)) * HW + p) * CG + (d & 31)] =
                acc[j][i] + bp[d];
        }
    }
}

// ---------------- K2: depthwise 3x3 conv + partial LN sums ----------------
__global__ __launch_bounds__(256) void k_dwconv(const float* __restrict__ x,
                                                const float* __restrict__ dww,
                                                const float* __restrict__ dwb) {
    int bc = blockIdx.x;
    int b = bc >> 8, c = bc & 255;
    const float* xp = x + (size_t)(b * Cc + c) * HW;
    float* outp = d_x1 + (size_t)(b * Cc + c) * HW;
    float wr[9];
#pragma unroll
    for (int t = 0; t < 9; t++) wr[t] = dww[c * 9 + t];
    float bias = dwb[c];
    double s1 = 0.0, s2 = 0.0;
    int tid = threadIdx.x;
    for (int p = tid; p < HW; p += 256) {
        int h = p >> 6, w = p & 63;
        float acc = bias;
#pragma unroll
        for (int dy = 0; dy < 3; dy++) {
            int yy = h + dy - 1;
            if ((unsigned)yy < (unsigned)Hh) {
#pragma unroll
                for (int dx = 0; dx < 3; dx++) {
                    int xx = w + dx - 1;
                    if ((unsigned)xx < (unsigned)Ww)
                        acc += xp[yy * Ww + xx] * wr[dy * 3 + dx];
                }
            }
        }
        outp[p] = acc;
        s1 += (double)acc;
        s2 += (double)acc * (double)acc;
    }
    __shared__ double rs1[256];
    __shared__ double rs2[256];
    rs1[tid] = s1;
    rs2[tid] = s2;
    __syncthreads();
    for (int off = 128; off > 0; off >>= 1) {
        if (tid < off) {
            rs1[tid] += rs1[tid + off];
            rs2[tid] += rs2[tid + off];
        }
        __syncthreads();
    }
    if (tid == 0) {
        atomicAdd(&d_stats[b * 2 + 0], rs1[0]);
        atomicAdd(&d_stats[b * 2 + 1], rs2[0]);
    }
}

// ---------------- K3: finalize LN stats -----------------------------------
__global__ void k_stats() {
    int b = threadIdx.x;
    if (b < Bz) {
        const double Np = (double)Cc * HW;
        double mu = d_stats[b * 2 + 0] / Np;
        double var = d_stats[b * 2 + 1] / Np - mu * mu;
        d_mustd[b * 2 + 0] = (float)mu;
        d_mustd[b * 2 + 1] = (float)(1.0 / sqrt(var + 1e-5));
    }
}

// ---------------- K4: apply LN + exact GELU in place ----------------------
__global__ __launch_bounds__(256) void k_lngelu() {
    size_t idx = (size_t)blockIdx.x * 256 + threadIdx.x;
    if (idx >= (size_t)Bz * Cc * HW) return;
    int b = (int)(idx / ((size_t)Cc * HW));
    float mu = d_mustd[b * 2 + 0];
    float istd = d_mustd[b * 2 + 1];
    float v = (d_x1[idx] - mu) * istd;
    d_x1[idx] = 0.5f * v * (1.f + erff(v * 0.70710678118654752f));
}

// ---------------- K5: heads conv as implicit-GEMM tf32 mma.sync -----------
// cp.async double-buffered staging. Block tile: 128 pixels x 112 co.
#define PATCH_F (2 * 8 * 4 * 72)     // 4608 floats
#define WS_F (2 * 112 * 76)          // 17024 floats
#define HEADS_SMEM ((PATCH_F + WS_F) * 4)  // 86528 bytes

__global__ __launch_bounds__(256) void k_heads_mma(const float* __restrict__ offw,
                                                   const float* __restrict__ offbias,
                                                   const float* __restrict__ maskw,
                                                   const float* __restrict__ maskbias) {
    extern __shared__ float dynsm[];
    float* patchp = dynsm;                 // [(buf*8+ci)*4+r]*72 + col
    float* wsp = dynsm + PATCH_F;          // [(buf*112+col)*76 + k]

    int b = blockIdx.z;
    int p0 = blockIdx.x * 128;
    int n0 = blockIdx.y * 112;
    int h0 = p0 >> 6;
    int tid = threadIdx.x;
    int warp = tid >> 5, lane = tid & 31;
    int wm = warp & 3, wn = warp >> 2;
    int lg = lane >> 2, lt = lane & 3;

    const float* x1b = d_x1 + (size_t)b * Cc * HW;
    uint32_t smem_u32 = (uint32_t)__cvta_generic_to_shared(dynsm);
    uint32_t ws_u32 = smem_u32 + PATCH_F * 4;

    // zero both buffers once (halo cols / invalid rows / co>=216 stay zero)
    for (int idx = tid; idx < PATCH_F + WS_F; idx += 256) dynsm[idx] = 0.f;
    __syncthreads();

    float acc[2][7][4];
#pragma unroll
    for (int mt = 0; mt < 2; mt++)
#pragma unroll
        for (int nt = 0; nt < 7; nt++)
#pragma unroll
            for (int e = 0; e < 4; e++) acc[mt][nt][e] = 0.f;

#define STAGE(CHUNK, BUF)                                                          \
    {                                                                              \
        int ci0_ = (CHUNK) * 8;                                                    \
        int kk0_ = ci0_ * 9;                                                       \
        for (int idx = tid; idx < 2528; idx += 256) {                              \
            if (idx < 512) {                                                       \
                int ciL = idx >> 6;                                                \
                int r = (idx >> 4) & 3;                                            \
                int j = idx & 15;                                                  \
                int gy = h0 - 1 + r;                                               \
                if ((unsigned)gy < (unsigned)Hh) {                                 \
                    const float* src =                                             \
                        x1b + (size_t)(ci0_ + ciL) * HW + gy * Ww + j * 4;         \
                    uint32_t dst = smem_u32 +                                      \
                        ((((BUF) * 8 + ciL) * 4 + r) * 72 + 4 + j * 4) * 4;        \
                    CP16(dst, src);                                                \
                }                                                                  \
            } else {                                                               \
                int t = idx - 512;                                                 \
                int col = t / 18;                                                  \
                int j = t - col * 18;                                              \
                int cog = n0 + col;                                                \
                if (cog < CO_ALL) {                                                \
                    const float* src =                                             \
                        (cog < CO_OFF ? offw + (size_t)cog * 2304                  \
                                      : maskw + (size_t)(cog - CO_OFF) * 2304) +   \
                        kk0_ + j * 4;                                              \
                    uint32_t dst =                                                 \
                        ws_u32 + (((BUF) * 112 + col) * 76 + j * 4) * 4;           \
                    CP16(dst, src);                                                \
                }                                                                  \
            }                                                                      \
        }                                                                          \
        CP_COMMIT();                                                               \
    }

    STAGE(0, 0);
    for (int c = 0; c < 32; c++) {
        int buf = c & 1;
        if (c < 31) {
            STAGE(c + 1, buf ^ 1);
        } else {
            CP_COMMIT();  // empty group keeps wait count uniform
        }
        CP_WAIT1();
        __syncthreads();

        const float* pb = patchp + (size_t)buf * 8 * 4 * 72;
        const float* wb = wsp + (size_t)buf * 112 * 76;
#pragma unroll
        for (int ks = 0; ks < 9; ks++) {
            int kb = ks * 8;
            int qa = kb + lt;
            int ciA = qa / 9; int ta = qa - ciA * 9;
            int kia = ta / 3; int kja = ta - kia * 3;
            int qb = qa + 4;
            int ciB = qb / 9; int tb = qb - ciB * 9;
            int kib = tb / 3; int kjb = tb - kib * 3;

            unsigned bfr[7][2];
#pragma unroll
            for (int nt = 0; nt < 7; nt++) {
                int n = wn * 56 + nt * 8 + lg;
                bfr[nt][0] = __float_as_uint(wb[n * 76 + kb + lt]);
                bfr[nt][1] = __float_as_uint(wb[n * 76 + kb + lt + 4]);
            }
#pragma unroll
            for (int mt = 0; mt < 2; mt++) {
                int rm = wm * 32 + mt * 16;
                int hL = rm >> 6;
                int w0 = (rm & 63) + lg;
                unsigned afr[4];
                afr[0] = __float_as_uint(pb[(ciA * 4 + hL + kia) * 72 + 3 + w0 + kja]);
                afr[1] = __float_as_uint(pb[(ciA * 4 + hL + kia) * 72 + 11 + w0 + kja]);
                afr[2] = __float_as_uint(pb[(ciB * 4 + hL + kib) * 72 + 3 + w0 + kjb]);
                afr[3] = __float_as_uint(pb[(ciB * 4 + hL + kib) * 72 + 11 + w0 + kjb]);
#pragma unroll
                for (int nt = 0; nt < 7; nt++) {
                    asm volatile(
                        "mma.sync.aligned.m16n8k8.row.col.f32.tf32.tf32.f32 "
                        "{%0,%1,%2,%3},{%4,%5,%6,%7},{%8,%9},{%0,%1,%2,%3};"
                        : "+f"(acc[mt][nt][0]), "+f"(acc[mt][nt][1]),
                          "+f"(acc[mt][nt][2]), "+f"(acc[mt][nt][3])
                        : "r"(afr[0]), "r"(afr[1]), "r"(afr[2]), "r"(afr[3]),
                          "r"(bfr[nt][0]), "r"(bfr[nt][1]));
                }
            }
        }
        __syncthreads();
    }
#undef STAGE

    // epilogue: bias + scatter to d_offb / d_maskb
#pragma unroll
    for (int mt = 0; mt < 2; mt++) {
        int rm = wm * 32 + mt * 16;
#pragma unroll
        for (int nt = 0; nt < 7; nt++) {
            int ncol = wn * 56 + nt * 8 + lt * 2;
#pragma unroll
            for (int e = 0; e < 4; e++) {
                int co = n0 + ncol + (e & 1);
                int p = p0 + rm + lg + ((e >> 1) * 8);
                float v = acc[mt][nt][e];
                if (co < CO_OFF)
                    d_offb[((size_t)b * CO_OFF + co) * HW + p] = v + offbias[co];
                else if (co < CO_ALL)
                    d_maskb[((size_t)b * CO_MASK + (co - CO_OFF)) * HW + p] =
                        v + maskbias[co - CO_OFF];
            }
        }
    }
}

// ---------------- K6: softmax over consecutive flat groups of 9 -----------
__global__ __launch_bounds__(256) void k_softmax() {
    __shared__ float sm[2304];
    int tid = threadIdx.x;
    size_t base = (size_t)blockIdx.x * 2304;
#pragma unroll
    for (int idx = tid; idx < 2304; idx += 256) sm[idx] = d_maskb[base + idx];
    __syncthreads();
    float* p = sm + tid * 9;
    float v[9];
    float mx = -1e30f;
#pragma unroll
    for (int i = 0; i < 9; i++) {
        v[i] = p[i];
        mx = fmaxf(mx, v[i]);
    }
    float s = 0.f;
#pragma unroll
    for (int i = 0; i < 9; i++) {
        v[i] = expf(v[i] - mx);
        s += v[i];
    }
    float inv = 1.f / s;
#pragma unroll
    for (int i = 0; i < 9; i++) p[i] = v[i] * inv;
    __syncthreads();
#pragma unroll
    for (int idx = tid; idx < 2304; idx += 256) d_maskb[base + idx] = sm[idx];
}

// ---------------- K7: deformable sampling + output einsum -----------------
#define WSM_F 9344
#define VS_F (8 * 4 * 288)
#define OUTB_F (32 * 129)
#define SAMPLE_SMEM ((WSM_F + VS_F + OUTB_F) * 4)  // 90752 bytes

__global__ __launch_bounds__(256) void k_sample(const float* __restrict__ outw,
                                                const float* __restrict__ outbias,
                                                float* __restrict__ out) {
    extern __shared__ float sm2[];
    float* wsm = sm2;
    float* vsbase = sm2 + WSM_F;
    float* outbf = sm2 + WSM_F + VS_F;

    int tid = threadIdx.x;
    int warp = tid >> 5, lane = tid & 31;
    int bg = blockIdx.x >> 5;
    int b = bg >> 3, g = bg & 7;
    int p0 = (blockIdx.x & 31) * 128;

    for (int idx = tid; idx < 32 * 288; idx += 256) {
        int o = idx / 288, k = idx - o * 288;
        wsm[o * 292 + k] = outw[(size_t)(g * OG + o) * 288 + k];
    }
    __syncthreads();

    const float* inpg = d_inp + (size_t)(b * Gg + g) * HW * CG;
    const float* offbase = d_offb + ((size_t)b * CO_OFF + g * 18) * HW;
    const float* mbase = d_maskb + ((size_t)b * CO_MASK + g * Nn) * HW;
    float* vsw = vsbase + warp * 4 * 288;
    const float4* wv = reinterpret_cast<const float4*>(&wsm[lane * 292]);

    int pbase = p0 + warp * 16;
#pragma unroll 1
    for (int pass = 0; pass < 4; pass++) {
#pragma unroll
        for (int i = 0; i < 4; i++) {
            int p = pbase + pass * 4 + i;
            int h = p >> 6, w = p & 63;
            const float* offp = offbase + p;
            const float* mp = mbase + p;
            float* vsd = vsw + i * 288;
#pragma unroll
            for (int n = 0; n < Nn; n++) {
                float dy = offp[(size_t)(n * 2) * HW];
                float dx = offp[(size_t)(n * 2 + 1) * HW];
                float m = mp[(size_t)n * HW];
                float py = dy + (float)(n / 3) + (float)(h - 1);
                float px = dx + (float)(n % 3) + (float)(w - 1);
                float fy = floorf(py), fx = floorf(px);
                int y0 = (int)fy, x0 = (int)fx;
                float wy = py - fy, wx = px - fx;
                float v = 0.f;
                {
                    int yi = y0, xi = x0;
                    if ((unsigned)yi < (unsigned)Hh && (unsigned)xi < (unsigned)Ww)
                        v += (1.f - wy) * (1.f - wx) *
                             inpg[(size_t)(yi * Ww + xi) * CG + lane];
                }
                {
                    int yi = y0, xi = x0 + 1;
                    if ((unsigned)yi < (unsigned)Hh && (unsigned)xi < (unsigned)Ww)
                        v += (1.f - wy) * wx *
                             inpg[(size_t)(yi * Ww + xi) * CG + lane];
                }
                {
                    int yi = y0 + 1, xi = x0;
                    if ((unsigned)yi < (unsigned)Hh && (unsigned)xi < (unsigned)Ww)
                        v += wy * (1.f - wx) *
                             inpg[(size_t)(yi * Ww + xi) * CG + lane];
                }
                {
                    int yi = y0 + 1, xi = x0 + 1;
                    if ((unsigned)yi < (unsigned)Hh && (unsigned)xi < (unsigned)Ww)
                        v += wy * wx * inpg[(size_t)(yi * Ww + xi) * CG + lane];
                }
                vsd[lane * 9 + n] = v * m;
            }
        }
        __syncwarp();

        const float4* v0 = reinterpret_cast<const float4*>(vsw);
        const float4* v1 = reinterpret_cast<const float4*>(vsw + 288);
        const float4* v2 = reinterpret_cast<const float4*>(vsw + 576);
        const float4* v3 = reinterpret_cast<const float4*>(vsw + 864);
        float a0 = 0.f, a1 = 0.f, a2 = 0.f, a3 = 0.f;
#pragma unroll 8
        for (int k = 0; k < 72; k++) {
            float4 ww = wv[k];
            float4 q;
            q = v0[k]; a0 += q.x * ww.x + q.y * ww.y + q.z * ww.z + q.w * ww.w;
            q = v1[k]; a1 += q.x * ww.x + q.y * ww.y + q.z * ww.z + q.w * ww.w;
            q = v2[k]; a2 += q.x * ww.x + q.y * ww.y + q.z * ww.z + q.w * ww.w;
            q = v3[k]; a3 += q.x * ww.x + q.y * ww.y + q.z * ww.z + q.w * ww.w;
        }
        int colb = warp * 16 + pass * 4;
        outbf[lane * 129 + colb + 0] = a0;
        outbf[lane * 129 + colb + 1] = a1;
        outbf[lane * 129 + colb + 2] = a2;
        outbf[lane * 129 + colb + 3] = a3;
        __syncwarp();
    }
    __syncthreads();

    for (int idx = tid; idx < 4096; idx += 256) {
        int o = idx >> 7, pp = idx & 127;
        out[((size_t)b * Oo + g * OG + o) * HW + p0 + pp] =
            outbf[o * 129 + pp] + outbias[g * OG + o];
    }
}

// ---------------- launcher -------------------------------------------------
// Capture-fork helpers: created once on first (non-capture) call; host-side
// objects only — no device memory involved. Work per call is identical.
static cudaStream_t g_side_stream() {
    static cudaStream_t s = [] {
        cudaStream_t t;
        cudaStreamCreateWithFlags(&t, cudaStreamNonBlocking);
        return t;
    }();
    return s;
}
static cudaEvent_t g_ev_fork() {
    static cudaEvent_t e = [] {
        cudaEvent_t t;
        cudaEventCreateWithFlags(&t, cudaEventDisableTiming);
        return t;
    }();
    return e;
}
static cudaEvent_t g_ev_join() {
    static cudaEvent_t e = [] {
        cudaEvent_t t;
        cudaEventCreateWithFlags(&t, cudaEventDisableTiming);
        return t;
    }();
    return e;
}

extern "C" void kernel_launch(void* const* d_in, const int* in_sizes, int n_in,
                              void* d_out, int out_size) {
    const float* x = (const float*)d_in[0];
    const float* in_proj_w = (const float*)d_in[1];
    const float* in_proj_b = (const float*)d_in[2];
    const float* dw_w = (const float*)d_in[3];
    const float* dw_b = (const float*)d_in[4];
    const float* off_w = (const float*)d_in[5];
    const float* off_b = (const float*)d_in[6];
    const float* mask_w = (const float*)d_in[7];
    const float* mask_b = (const float*)d_in[8];
    const float* out_w = (const float*)d_in[9];
    const float* out_b = (const float*)d_in[10];
    float* out = (float*)d_out;

    cudaFuncSetAttribute(k_heads_mma, cudaFuncAttributeMaxDynamicSharedMemorySize,
                         HEADS_SMEM);
    cudaFuncSetAttribute(k_sample, cudaFuncAttributeMaxDynamicSharedMemorySize,
                         SAMPLE_SMEM);

    cudaStream_t s2 = g_side_stream();
    cudaEvent_t eF = g_ev_fork();
    cudaEvent_t eJ = g_ev_join();

    // ---- fork: inproj runs on a parallel branch (only k_sample needs d_inp)
    cudaEventRecord(eF, 0);
    cudaStreamWaitEvent(s2, eF, 0);
    {
        dim3 grid(HW / 64, Oo / 64, Bz);
        k_inproj<<<grid, 256, 0, s2>>>(x, in_proj_w, in_proj_b);
    }
    cudaEventRecord(eJ, s2);

    // ---- main branch: dwconv -> stats -> lngelu -> heads -> softmax
    k_zero_stats<<<1, 32>>>();
    k_dwconv<<<Bz * Cc, 256>>>(x, dw_w, dw_b);
    k_stats<<<1, 32>>>();
    {
        int total = Bz * Cc * HW;
        k_lngelu<<<(total + 255) / 256, 256>>>();
    }
    {
        dim3 grid(HW / 128, 2, Bz);
        k_heads_mma<<<grid, 256, HEADS_SMEM>>>(off_w, off_b, mask_w, mask_b);
    }
    k_softmax<<<512, 256>>>();

    // ---- join: sample needs d_inp + d_offb + d_maskb
    cudaStreamWaitEvent(0, eJ, 0);
    k_sample<<<1024, 256, SAMPLE_SMEM>>>(out_w, out_b, out);
}